// round 1
// baseline (speedup 1.0000x reference)
#include <cuda_runtime.h>
#include <cstdint>

#define BATCH 128
#define CH    32
#define LPOS  4096
#define POS   8      // positions per CTA (one per warp)
#define TPB   256
#define BB    4      // batches per group

__device__ __forceinline__ unsigned long long pack2(float lo, float hi) {
    unsigned long long r;
    asm("mov.b64 %0, {%1, %2};" : "=l"(r) : "f"(lo), "f"(hi));
    return r;
}

__device__ __forceinline__ void fma2(unsigned long long& d,
                                     unsigned long long a,
                                     unsigned long long b) {
    // d = a * b + d  (two packed fp32 FMAs per instruction, Blackwell f32x2)
    asm("fma.rn.f32x2 %0, %1, %2, %0;" : "+l"(d) : "l"(a), "l"(b));
}

__global__ __launch_bounds__(TPB)
void dyna_dec_kernel(const float* __restrict__ x,
                     const float* __restrict__ weight,
                     const float* __restrict__ bias,
                     float* __restrict__ out)
{
    // x staging: index (c*POS + l)*BB + b  == linear i, 1024 floats
    __shared__ float xs[BB * CH * POS];
    // out staging: index d*36 + l*4 + b   (stride 36 kills STS.128 bank conflicts)
    __shared__ float os[CH * 36];

    const int tid  = threadIdx.x;
    const int warp = tid >> 5;      // local position index
    const int lane = tid & 31;      // output channel d
    const int l0   = blockIdx.x * POS;
    const int gl   = l0 + warp;     // global position this warp owns

    // Per-lane weights for (gl, c, lane), c = 0..31. Coalesced 128B per c.
    // Pre-packed as (w, w) for f32x2.
    unsigned long long wp[CH];
    const float* wptr = weight + (size_t)gl * (CH * CH) + lane;
#pragma unroll
    for (int c = 0; c < CH; c++) {
        float w = wptr[c * CH];
        wp[c] = pack2(w, w);
    }
    const float bv = bias[gl * CH + lane];
    const unsigned long long bvp = pack2(bv, bv);

    for (int b0 = 0; b0 < BATCH; b0 += BB) {
        __syncthreads();   // (a) xs free (prev compute done), os free (prev stores done)

        // Stage x: i -> b=i&3, l=(i>>2)&7, c=i>>5.
        // Global: per warp 4 b-rows x 8 contiguous l = 4 fully-used 32B sectors.
        // SMEM: consecutive i -> consecutive address, conflict-free.
#pragma unroll
        for (int k = 0; k < 4; k++) {
            int i  = tid + k * TPB;
            int bi = i & 3;
            int li = (i >> 2) & 7;
            int ci = i >> 5;
            xs[i] = x[(size_t)(b0 + bi) * (CH * LPOS) + ci * LPOS + l0 + li];
        }
        __syncthreads();   // (b) xs visible

        unsigned long long a01 = bvp;
        unsigned long long a23 = bvp;
        // Broadcast LDS.128: all lanes read same address -> N=1, no conflict.
        const ulonglong2* xp =
            reinterpret_cast<const ulonglong2*>(xs) + warp;   // ull2 index = c*POS + warp
#pragma unroll
        for (int c = 0; c < CH; c++) {
            ulonglong2 xv = xp[c * POS];   // (x[b0],x[b1]) , (x[b2],x[b3])
            fma2(a01, xv.x, wp[c]);
            fma2(a23, xv.y, wp[c]);
        }

        // Unpack and stage to os (padded layout: conflict-free STS.128 phases)
        float4 ov;
        asm("mov.b64 {%0, %1}, %2;" : "=f"(ov.x), "=f"(ov.y) : "l"(a01));
        asm("mov.b64 {%0, %1}, %2;" : "=f"(ov.z), "=f"(ov.w) : "l"(a23));
        *reinterpret_cast<float4*>(os + lane * 36 + warp * 4) = ov;

        __syncthreads();   // (c) os visible across warps

        // Store out: same i-mapping as x staging -> fully-used 32B sectors.
        // SMEM reads: per warp d const, addr = l*4+b consecutive, conflict-free.
#pragma unroll
        for (int k = 0; k < 4; k++) {
            int i  = tid + k * TPB;
            int bi = i & 3;
            int li = (i >> 2) & 7;
            int d  = i >> 5;
            out[(size_t)(b0 + bi) * (CH * LPOS) + d * LPOS + l0 + li] =
                os[d * 36 + li * 4 + bi];
        }
    }
}

extern "C" void kernel_launch(void* const* d_in, const int* in_sizes, int n_in,
                              void* d_out, int out_size)
{
    // metadata order: x [B,C,H,W] f32, px [1] f32 (unused), weight [L*C, C] f32, bias [L*C] f32
    const float* x      = (const float*)d_in[0];
    const float* weight = (const float*)d_in[2];
    const float* bias   = (const float*)d_in[3];
    float* out          = (float*)d_out;

    dyna_dec_kernel<<<LPOS / POS, TPB>>>(x, weight, bias, out);
}

// round 3
// speedup vs baseline: 1.3852x; 1.3852x over previous
#include <cuda_runtime.h>
#include <cstdint>

#define BATCH 128
#define CH    32
#define LPOS  4096
#define POS   8       // positions per CTA (one per warp)
#define TPB   256
#define BB    8       // batches per group
#define NG    (BATCH / BB)            // 16 groups
#define XS_ELEMS (CH * POS * BB)      // 2048 floats per buffer
#define OS_STRIDE 68                  // floats; 272B, 16B-aligned, conflict-free STS.128

__device__ __forceinline__ unsigned long long pack2(float lo, float hi) {
    unsigned long long r;
    asm("mov.b64 %0, {%1, %2};" : "=l"(r) : "f"(lo), "f"(hi));
    return r;
}

__device__ __forceinline__ void fma2(unsigned long long& d,
                                     unsigned long long a,
                                     unsigned long long b) {
    // two packed fp32 FMAs per instruction (Blackwell f32x2, PTX-only)
    asm("fma.rn.f32x2 %0, %1, %2, %0;" : "+l"(d) : "l"(a), "l"(b));
}

__device__ __forceinline__ uint32_t smem_u32(const void* p) {
    uint32_t a;
    asm("{ .reg .u64 t; cvta.to.shared.u64 t, %1; cvt.u32.u64 %0, t; }"
        : "=r"(a) : "l"(p));
    return a;
}

__device__ __forceinline__ void cp_async4(uint32_t dst, const float* src) {
    asm volatile("cp.async.ca.shared.global [%0], [%1], 4;\n"
                 :: "r"(dst), "l"(src));
}

__global__ __launch_bounds__(TPB)
void dyna_dec_kernel(const float* __restrict__ x,
                     const float* __restrict__ weight,
                     const float* __restrict__ bias,
                     float* __restrict__ out)
{
    // xs layout: [c][l][b] -> index c*64 + l*8 + b (b fastest => LDS.128 over 4 b)
    __shared__ __align__(16) float xs[2][XS_ELEMS];
    // os layout: [d][l][b] with padded stride: d*68 + l*8 + b
    __shared__ __align__(16) float os[CH * OS_STRIDE];

    const int tid  = threadIdx.x;
    const int warp = tid >> 5;       // local position
    const int lane = tid & 31;       // output channel d
    const int l0   = blockIdx.x * POS;
    const int gl   = l0 + warp;

    // ---- per-lane weights, packed (w,w) for f32x2 ----
    unsigned long long wp[CH];
    {
        const float* wptr = weight + (size_t)gl * (CH * CH) + lane;
#pragma unroll
        for (int c = 0; c < CH; c++) {
            float w = wptr[c * CH];
            wp[c] = pack2(w, w);
        }
    }
    const float bv = bias[gl * CH + lane];
    const unsigned long long bvp = pack2(bv, bv);

    // ---- staging decomposition (thread -> element, decoupled from xs layout) ----
    // i = tid + k*TPB ;  c = i>>6 (= c0 + 4k), b = (i>>3)&7, l = i&7
    // => 8 consecutive lanes read 8 contiguous l: full 32B sectors.
    const int b_s = (tid >> 3) & 7;
    const int l_s = tid & 7;
    const int c0  = tid >> 6;        // 0..3

    const float* gsrc = x + (size_t)b_s * (CH * LPOS) + (size_t)c0 * LPOS + l0 + l_s;
    const int dst0 = c0 * (POS * BB) + l_s * BB + b_s;   // xs element index
    const uint32_t xs_a0 = smem_u32(&xs[0][0]) + dst0 * 4;
    const uint32_t xs_a1 = smem_u32(&xs[1][0]) + dst0 * 4;

    // prologue: stage group 0 into buffer 0
#pragma unroll
    for (int k = 0; k < 8; k++)
        cp_async4(xs_a0 + k * (TPB * 4), gsrc + (size_t)k * 4 * LPOS);
    asm volatile("cp.async.commit_group;" ::: "memory");

#pragma unroll 1
    for (int g = 0; g < NG; g++) {
        const int buf = g & 1;

        if (g + 1 < NG) {
            const float* s = gsrc + (size_t)(g + 1) * BB * (CH * LPOS);
            const uint32_t d = (buf ? xs_a0 : xs_a1);
#pragma unroll
            for (int k = 0; k < 8; k++)
                cp_async4(d + k * (TPB * 4), s + (size_t)k * 4 * LPOS);
            asm volatile("cp.async.commit_group;" ::: "memory");
            asm volatile("cp.async.wait_group 1;" ::: "memory");
        } else {
            asm volatile("cp.async.wait_group 0;" ::: "memory");
        }
        __syncthreads();   // xs[buf] visible to all; os reads of g-1 complete

        // ---- compute: 8 batches x lane's channel d ----
        unsigned long long a01 = bvp, a23 = bvp, a45 = bvp, a67 = bvp;
        const ulonglong2* xp =
            reinterpret_cast<const ulonglong2*>(&xs[buf][warp * BB]);
        // per c: two LDS.128 broadcasts (b0..3, b4..7) + 4 FFMA2
#pragma unroll
        for (int c = 0; c < CH; c++) {
            ulonglong2 xv0 = xp[c * (POS * BB / 4)];       // floats c*64 + warp*8 + 0..3
            ulonglong2 xv1 = xp[c * (POS * BB / 4) + 1];   // floats ... + 4..7
            fma2(a01, xv0.x, wp[c]);
            fma2(a23, xv0.y, wp[c]);
            fma2(a45, xv1.x, wp[c]);
            fma2(a67, xv1.y, wp[c]);
        }

        // stage to os (conflict-free STS.128: d*68 mod 32 = d*4)
        float4 o0, o1;
        asm("mov.b64 {%0, %1}, %2;" : "=f"(o0.x), "=f"(o0.y) : "l"(a01));
        asm("mov.b64 {%0, %1}, %2;" : "=f"(o0.z), "=f"(o0.w) : "l"(a23));
        asm("mov.b64 {%0, %1}, %2;" : "=f"(o1.x), "=f"(o1.y) : "l"(a45));
        asm("mov.b64 {%0, %1}, %2;" : "=f"(o1.z), "=f"(o1.w) : "l"(a67));
        float* op = os + lane * OS_STRIDE + warp * BB;
        *reinterpret_cast<float4*>(op)     = o0;
        *reinterpret_cast<float4*>(op + 4) = o1;

        __syncthreads();   // os visible across warps

        // ---- store out: same (b,l,c)->thread mapping => full 32B sectors ----
        {
            const int b0g = g * BB;
            float* gdst = out + (size_t)(b0g + b_s) * (CH * LPOS)
                              + (size_t)c0 * LPOS + l0 + l_s;
            const float* osrc = os + c0 * OS_STRIDE + l_s * BB + b_s;
#pragma unroll
            for (int k = 0; k < 8; k++)
                gdst[(size_t)k * 4 * LPOS] = osrc[k * 4 * OS_STRIDE];
        }
    }
}

extern "C" void kernel_launch(void* const* d_in, const int* in_sizes, int n_in,
                              void* d_out, int out_size)
{
    // metadata order: x [B,C,H,W] f32, px [1] f32 (unused), weight [L*C,C] f32, bias [L*C] f32
    const float* x      = (const float*)d_in[0];
    const float* weight = (const float*)d_in[2];
    const float* bias   = (const float*)d_in[3];
    float* out          = (float*)d_out;

    dyna_dec_kernel<<<LPOS / POS, TPB>>>(x, weight, bias, out);
}